// round 10
// baseline (speedup 1.0000x reference)
#include <cuda_runtime.h>

#define Bc 2
#define Tc 2048
#define Cc 512
#define Hc 8
#define HDc 64
#define TOPKc 64
#define BHc (Bc*Hc)
#define Mr (Bc*Tc)
#define QT 8
#define KT 128

// Scratch (device globals; allocations forbidden)
__device__ float g_Qh[BHc*Tc*HDc];
__device__ float g_Kh[BHc*Tc*HDc];
__device__ float g_Vh[BHc*Tc*HDc];
__device__ float g_Y [Bc*Tc*Cc];

// ---------------------------------------------------------------------------
// helpers
// ---------------------------------------------------------------------------
__device__ __forceinline__ unsigned f2u(float f) {
    unsigned b = __float_as_uint(f);
    return b ^ ((unsigned)((int)b >> 31) | 0x80000000u);
}
__device__ __forceinline__ float u2f(unsigned u) {
    unsigned b = (u & 0x80000000u) ? (u ^ 0x80000000u) : ~u;
    return __uint_as_float(b);
}

// ---------------------------------------------------------------------------
// Fused QKV GEMM (round-8 exact, measured 157us): BM=BN=128, BK=8, 256 thr,
// scalar FFMA 8x8 micro, double buffer. z==2 (V): fused per-head row-norm.
// ---------------------------------------------------------------------------
__global__ void __launch_bounds__(256, 2)
qkv_kernel(const float* __restrict__ A,
           const float* __restrict__ Wq, const float* __restrict__ bq,
           const float* __restrict__ Wk, const float* __restrict__ bk,
           const float* __restrict__ Wv, const float* __restrict__ bv,
           float* __restrict__ Qh, float* __restrict__ Kh, float* __restrict__ Vh)
{
    int z = blockIdx.z;
    const float* W    = (z == 0) ? Wq : (z == 1) ? Wk : Wv;
    const float* bias = (z == 0) ? bq : (z == 1) ? bk : bv;
    float* out        = (z == 0) ? Qh : (z == 1) ? Kh : Vh;

    __shared__ float As[2][8][128];
    __shared__ float Bs[2][8][128];

    int tid = threadIdx.x;
    int bm = blockIdx.y * 128;
    int bn = blockIdx.x * 128;
    int ty = tid >> 4;
    int tx = tid & 15;

    int arow = tid >> 1;
    int akq  = (tid & 1) * 4;
    int brow = tid >> 5;
    int bcol = (tid & 31) * 4;

    const float* Ag = A + (size_t)(bm + arow) * Cc + akq;
    const float* Wg = W + (size_t)brow * Cc + bn + bcol;

    float acc[8][8];
    #pragma unroll
    for (int i = 0; i < 8; i++)
        #pragma unroll
        for (int j = 0; j < 8; j++) acc[i][j] = 0.f;

    {
        float4 av = *reinterpret_cast<const float4*>(Ag);
        float4 bv4 = *reinterpret_cast<const float4*>(Wg);
        As[0][akq + 0][arow] = av.x;
        As[0][akq + 1][arow] = av.y;
        As[0][akq + 2][arow] = av.z;
        As[0][akq + 3][arow] = av.w;
        *reinterpret_cast<float4*>(&Bs[0][brow][bcol]) = bv4;
    }
    __syncthreads();

    #pragma unroll 1
    for (int kb = 0; kb < 64; kb++) {
        int cur = kb & 1;
        float4 an, bnv;
        if (kb < 63) {
            an  = *reinterpret_cast<const float4*>(Ag + (kb + 1) * 8);
            bnv = *reinterpret_cast<const float4*>(Wg + (size_t)(kb + 1) * 8 * Cc);
        }
        #pragma unroll
        for (int k = 0; k < 8; k++) {
            float4 a0 = *reinterpret_cast<const float4*>(&As[cur][k][ty * 4]);
            float4 a1 = *reinterpret_cast<const float4*>(&As[cur][k][64 + ty * 4]);
            float4 b0 = *reinterpret_cast<const float4*>(&Bs[cur][k][tx * 4]);
            float4 b1 = *reinterpret_cast<const float4*>(&Bs[cur][k][64 + tx * 4]);
            float a[8] = {a0.x, a0.y, a0.z, a0.w, a1.x, a1.y, a1.z, a1.w};
            float b[8] = {b0.x, b0.y, b0.z, b0.w, b1.x, b1.y, b1.z, b1.w};
            #pragma unroll
            for (int i = 0; i < 8; i++)
                #pragma unroll
                for (int j = 0; j < 8; j++)
                    acc[i][j] += a[i] * b[j];
        }
        if (kb < 63) {
            int nxt = cur ^ 1;
            As[nxt][akq + 0][arow] = an.x;
            As[nxt][akq + 1][arow] = an.y;
            As[nxt][akq + 2][arow] = an.z;
            As[nxt][akq + 3][arow] = an.w;
            *reinterpret_cast<float4*>(&Bs[nxt][brow][bcol]) = bnv;
            __syncthreads();
        }
    }

    float4 bia0 = *reinterpret_cast<const float4*>(bias + bn + tx * 4);
    float4 bia1 = *reinterpret_cast<const float4*>(bias + bn + 64 + tx * 4);
    #pragma unroll
    for (int i = 0; i < 8; i++) {
        int r = (i < 4) ? (ty * 4 + i) : (64 + ty * 4 + (i - 4));
        int mrow = bm + r;
        int b = mrow >> 11;
        int t = mrow & (Tc - 1);
        float4 o0 = make_float4(acc[i][0] + bia0.x, acc[i][1] + bia0.y,
                                acc[i][2] + bia0.z, acc[i][3] + bia0.w);
        float4 o1 = make_float4(acc[i][4] + bia1.x, acc[i][5] + bia1.y,
                                acc[i][6] + bia1.z, acc[i][7] + bia1.w);
        if (z == 2) {
            float ss0 = o0.x*o0.x + o0.y*o0.y + o0.z*o0.z + o0.w*o0.w;
            float ss1 = o1.x*o1.x + o1.y*o1.y + o1.z*o1.z + o1.w*o1.w;
            #pragma unroll
            for (int off = 8; off; off >>= 1) {
                ss0 += __shfl_xor_sync(0xffffffffu, ss0, off);
                ss1 += __shfl_xor_sync(0xffffffffu, ss1, off);
            }
            float sc0 = 1.0f / fmaxf(sqrtf(ss0), 1e-12f);
            float sc1 = 1.0f / fmaxf(sqrtf(ss1), 1e-12f);
            o0.x *= sc0; o0.y *= sc0; o0.z *= sc0; o0.w *= sc0;
            o1.x *= sc1; o1.y *= sc1; o1.z *= sc1; o1.w *= sc1;
        }
        int n0 = bn + tx * 4;       int h0 = n0 >> 6, d0 = n0 & 63;
        int n1 = bn + 64 + tx * 4;  int h1 = n1 >> 6, d1 = n1 & 63;
        *reinterpret_cast<float4*>(out + ((size_t)((b * Hc + h0) * Tc + t) << 6) + d0) = o0;
        *reinterpret_cast<float4*>(out + ((size_t)((b * Hc + h1) * Tc + t) << 6) + d1) = o1;
    }
}

// ---------------------------------------------------------------------------
// Output projection GEMM (row-major out), scalar FFMA (round-8 exact).
// ---------------------------------------------------------------------------
__global__ void __launch_bounds__(256, 2)
sgemm_kernel(const float* __restrict__ A, const float* __restrict__ W,
             const float* __restrict__ bias, float* __restrict__ out)
{
    __shared__ float As[2][8][128];
    __shared__ float Bs[2][8][128];

    int tid = threadIdx.x;
    int bm = blockIdx.y * 128;
    int bn = blockIdx.x * 128;
    int ty = tid >> 4;
    int tx = tid & 15;

    int arow = tid >> 1;
    int akq  = (tid & 1) * 4;
    int brow = tid >> 5;
    int bcol = (tid & 31) * 4;

    const float* Ag = A + (size_t)(bm + arow) * Cc + akq;
    const float* Wg = W + (size_t)brow * Cc + bn + bcol;

    float acc[8][8];
    #pragma unroll
    for (int i = 0; i < 8; i++)
        #pragma unroll
        for (int j = 0; j < 8; j++) acc[i][j] = 0.f;

    {
        float4 av = *reinterpret_cast<const float4*>(Ag);
        float4 bv4 = *reinterpret_cast<const float4*>(Wg);
        As[0][akq + 0][arow] = av.x;
        As[0][akq + 1][arow] = av.y;
        As[0][akq + 2][arow] = av.z;
        As[0][akq + 3][arow] = av.w;
        *reinterpret_cast<float4*>(&Bs[0][brow][bcol]) = bv4;
    }
    __syncthreads();

    #pragma unroll 1
    for (int kb = 0; kb < 64; kb++) {
        int cur = kb & 1;
        float4 an, bnv;
        if (kb < 63) {
            an  = *reinterpret_cast<const float4*>(Ag + (kb + 1) * 8);
            bnv = *reinterpret_cast<const float4*>(Wg + (size_t)(kb + 1) * 8 * Cc);
        }
        #pragma unroll
        for (int k = 0; k < 8; k++) {
            float4 a0 = *reinterpret_cast<const float4*>(&As[cur][k][ty * 4]);
            float4 a1 = *reinterpret_cast<const float4*>(&As[cur][k][64 + ty * 4]);
            float4 b0 = *reinterpret_cast<const float4*>(&Bs[cur][k][tx * 4]);
            float4 b1 = *reinterpret_cast<const float4*>(&Bs[cur][k][64 + tx * 4]);
            float a[8] = {a0.x, a0.y, a0.z, a0.w, a1.x, a1.y, a1.z, a1.w};
            float b[8] = {b0.x, b0.y, b0.z, b0.w, b1.x, b1.y, b1.z, b1.w};
            #pragma unroll
            for (int i = 0; i < 8; i++)
                #pragma unroll
                for (int j = 0; j < 8; j++)
                    acc[i][j] += a[i] * b[j];
        }
        if (kb < 63) {
            int nxt = cur ^ 1;
            As[nxt][akq + 0][arow] = an.x;
            As[nxt][akq + 1][arow] = an.y;
            As[nxt][akq + 2][arow] = an.z;
            As[nxt][akq + 3][arow] = an.w;
            *reinterpret_cast<float4*>(&Bs[nxt][brow][bcol]) = bnv;
            __syncthreads();
        }
    }

    float4 bia0 = *reinterpret_cast<const float4*>(bias + bn + tx * 4);
    float4 bia1 = *reinterpret_cast<const float4*>(bias + bn + 64 + tx * 4);
    #pragma unroll
    for (int i = 0; i < 8; i++) {
        int r = (i < 4) ? (ty * 4 + i) : (64 + ty * 4 + (i - 4));
        int mrow = bm + r;
        float4 o0 = make_float4(acc[i][0] + bia0.x, acc[i][1] + bia0.y,
                                acc[i][2] + bia0.z, acc[i][3] + bia0.w);
        float4 o1 = make_float4(acc[i][4] + bia1.x, acc[i][5] + bia1.y,
                                acc[i][6] + bia1.z, acc[i][7] + bia1.w);
        *reinterpret_cast<float4*>(out + (size_t)mrow * Cc + bn + tx * 4) = o0;
        *reinterpret_cast<float4*>(out + (size_t)mrow * Cc + bn + 64 + tx * 4) = o1;
    }
}

// ---------------------------------------------------------------------------
// Attention: round-8 exact EXCEPT the radix histogram update: colliding
// per-lane atomics -> match_any leader + one conflict-free atomicAdd per
// distinct bin per iteration (identical counts; removes ATOMS serialization).
// ---------------------------------------------------------------------------
struct AttnSmem {
    float qs[QT][HDc];                 // 2 KB
    float kt[KT][68];                  // 34.8 KB
    unsigned su[QT][Tc];               // 64 KB scores / probs
    union RowSel {
        int hist[256];
        unsigned short sidx[512];
    } sel[QT];                         // 8 KB
};

__global__ void __launch_bounds__(256, 2)
attn_kernel(const float* __restrict__ Q, const float* __restrict__ K,
            const float* __restrict__ V, float* __restrict__ Y)
{
    extern __shared__ unsigned char raw[];
    AttnSmem* S = reinterpret_cast<AttnSmem*>(raw);

    int tid  = threadIdx.x;
    int warp = tid >> 5;
    int lane = tid & 31;

    int bh = blockIdx.y;
    int qbase = ((int)gridDim.x - 1 - (int)blockIdx.x) * QT;  // long rows first
    int n_max = qbase + QT;

    const float* Kb = K + (size_t)bh * Tc * HDc;
    const float* Vb = V + (size_t)bh * Tc * HDc;

    if (tid < 128) {
        int r = tid >> 4, i = tid & 15;
        reinterpret_cast<float4*>(S->qs[r])[i] =
            reinterpret_cast<const float4*>(Q + ((size_t)bh * Tc + qbase + r) * HDc)[i];
    }

    // score-phase mapping: 4 rows x quarter keys per warp
    int quarter = warp >> 1;            // 0..3 -> key quarter
    int rgrp = (warp & 1) * 4;          // row group base (4 rows)
    int kqoff = quarter * 32 + lane;    // key offset within tile
    const float4* q40 = reinterpret_cast<const float4*>(S->qs[rgrp + 0]);
    const float4* q41 = reinterpret_cast<const float4*>(S->qs[rgrp + 1]);
    const float4* q42 = reinterpret_cast<const float4*>(S->qs[rgrp + 2]);
    const float4* q43 = reinterpret_cast<const float4*>(S->qs[rgrp + 3]);

    int ldrow = tid >> 4;               // 0..15
    int lddq  = (tid & 15) * 4;

    int ntiles = (n_max + KT - 1) / KT;

    // prologue: tile 0 -> registers
    float4 rv[8];
    #pragma unroll
    for (int i = 0; i < 8; i++)
        rv[i] = *reinterpret_cast<const float4*>(Kb + (size_t)(ldrow + 16 * i) * HDc + lddq);

    #pragma unroll 1
    for (int t = 0; t < ntiles; t++) {
        __syncthreads();
        #pragma unroll
        for (int i = 0; i < 8; i++)
            *reinterpret_cast<float4*>(&S->kt[ldrow + 16 * i][lddq]) = rv[i];
        __syncthreads();

        if (t + 1 < ntiles) {
            int t0n = (t + 1) * KT;
            #pragma unroll
            for (int i = 0; i < 8; i++)
                rv[i] = *reinterpret_cast<const float4*>(
                            Kb + (size_t)(t0n + ldrow + 16 * i) * HDc + lddq);
        }

        float a0 = 0.f, a1 = 0.f, a2 = 0.f, a3 = 0.f;
        #pragma unroll
        for (int i = 0; i < 16; i++) {
            float4 kv = *reinterpret_cast<const float4*>(&S->kt[kqoff][i * 4]);
            float4 qa = q40[i], qb = q41[i], qc = q42[i], qd = q43[i];
            a0 += qa.x * kv.x + qa.y * kv.y + qa.z * kv.z + qa.w * kv.w;
            a1 += qb.x * kv.x + qb.y * kv.y + qb.z * kv.z + qb.w * kv.w;
            a2 += qc.x * kv.x + qc.y * kv.y + qc.z * kv.z + qc.w * kv.w;
            a3 += qd.x * kv.x + qd.y * kv.y + qd.z * kv.z + qd.w * kv.w;
        }
        int k = t * KT + kqoff;
        if (k <= qbase + rgrp + 0) S->su[rgrp + 0][k] = f2u(a0 * 0.125f);
        if (k <= qbase + rgrp + 1) S->su[rgrp + 1][k] = f2u(a1 * 0.125f);
        if (k <= qbase + rgrp + 2) S->su[rgrp + 2][k] = f2u(a2 * 0.125f);
        if (k <= qbase + rgrp + 3) S->su[rgrp + 3][k] = f2u(a3 * 0.125f);
    }
    __syncthreads();   // all scores visible; switch to warp<->row mapping

    int row = warp;
    int qi = qbase + row;
    int n = qi + 1;
    unsigned* su = S->su[row];
    int* hist = S->sel[row].hist;

    // ---- exact rank-64 threshold: 4-pass byte radix.
    // Histogram update: match_any leader + ONE atomicAdd per distinct bin
    // per iteration (leaders hold distinct bins -> conflict-free ATOMS).
    unsigned thrU = 0u;
    if (n > TOPKc) {
        unsigned pref = 0u; int need = TOPKc;
        #pragma unroll 1
        for (int by = 3; by >= 0; --by) {
            int sh = by * 8;
            #pragma unroll
            for (int b = lane; b < 256; b += 32) hist[b] = 0;
            __syncwarp();
            unsigned hp = (by < 3) ? (pref >> (sh + 8)) : 0u;
            #pragma unroll 1
            for (int k0 = 0; k0 < n; k0 += 32) {
                int k = k0 + lane;
                bool valid = k < n;
                unsigned u = valid ? su[k] : 0u;
                bool sel = valid && (by == 3 || (u >> (sh + 8)) == hp);
                unsigned byte = (u >> sh) & 255u;
                unsigned pm = __ballot_sync(0xffffffffu, sel);
                unsigned mm = __match_any_sync(0xffffffffu, byte) & pm;
                if (sel && lane == (__ffs(mm) - 1))
                    atomicAdd(&hist[byte], __popc(mm));
            }
            __syncwarp();
            int s = 0;
            #pragma unroll
            for (int j = 0; j < 8; j++) s += hist[255 - lane * 8 - j];
            int cum = s;
            #pragma unroll
            for (int off = 1; off < 32; off <<= 1) {
                int v = __shfl_up_sync(0xffffffffu, cum, off);
                if (lane >= off) cum += v;
            }
            unsigned bal = __ballot_sync(0xffffffffu, cum >= need);
            int selL = __ffs(bal) - 1;
            int above = __shfl_sync(0xffffffffu, cum - s, selL);
            int sneed = need - above;
            int res = 0;
            if (lane == selL) {
                int c = 0;
                #pragma unroll 1
                for (int j = 0; j < 8; j++) {
                    int b = 255 - selL * 8 - j;
                    int h = hist[b];
                    if (c + h >= sneed) { res = (b << 16) | (sneed - c); break; }
                    c += h;
                }
            }
            res = __shfl_sync(0xffffffffu, res, selL);
            pref |= (unsigned)(res >> 16) << sh;
            need = res & 0xffff;
        }
        thrU = pref;
    }
    __syncwarp();

    // ---- ballot compaction (ordered) + row max
    unsigned short* sidx = S->sel[row].sidx;
    int m = 0; unsigned umax = 0u;
    #pragma unroll 1
    for (int k0 = 0; k0 < n; k0 += 32) {
        int k = k0 + lane;
        bool a = k < n;
        unsigned u = a ? su[k] : 0u;
        umax = max(umax, u);
        bool keep = a && (u >= thrU);
        unsigned bal = __ballot_sync(0xffffffffu, keep);
        if (keep) {
            int pos = m + __popc(bal & ((1u << lane) - 1u));
            if (pos < 512) sidx[pos] = (unsigned short)k;
        }
        m += __popc(bal);
    }
    if (m > 512) m = 512;
    #pragma unroll
    for (int off = 16; off; off >>= 1)
        umax = max(umax, __shfl_xor_sync(0xffffffffu, umax, off));

    // ---- softmax over survivors (probs overwrite su in place)
    float maxf = u2f(umax);
    float lsum = 0.f;
    for (int j = lane; j < m; j += 32) {
        int k = sidx[j];
        float p = __expf(u2f(su[k]) - maxf);
        su[k] = __float_as_uint(p);
        lsum += p;
    }
    __syncwarp();
    #pragma unroll
    for (int off = 16; off; off >>= 1) lsum += __shfl_xor_sync(0xffffffffu, lsum, off);
    float rinv = 1.0f / lsum;

    // ---- sparse PV (round-8 form)
    const float2* V2 = reinterpret_cast<const float2*>(Vb);
    float2 y = make_float2(0.f, 0.f);
    int j = 0;
    for (; j + 4 <= m; j += 4) {
        int k0 = sidx[j + 0], k1 = sidx[j + 1], k2 = sidx[j + 2], k3 = sidx[j + 3];
        float p0 = __uint_as_float(su[k0]);
        float p1 = __uint_as_float(su[k1]);
        float p2 = __uint_as_float(su[k2]);
        float p3 = __uint_as_float(su[k3]);
        float2 v0 = V2[(size_t)k0 * 32 + lane];
        float2 v1 = V2[(size_t)k1 * 32 + lane];
        float2 v2 = V2[(size_t)k2 * 32 + lane];
        float2 v3 = V2[(size_t)k3 * 32 + lane];
        y.x += p0 * v0.x + p1 * v1.x + p2 * v2.x + p3 * v3.x;
        y.y += p0 * v0.y + p1 * v1.y + p2 * v2.y + p3 * v3.y;
    }
    for (; j < m; j++) {
        int k = sidx[j];
        float p = __uint_as_float(su[k]);
        float2 v = V2[(size_t)k * 32 + lane];
        y.x += p * v.x; y.y += p * v.y;
    }
    int b = bh >> 3, h = bh & 7;
    *reinterpret_cast<float2*>(Y + (size_t)(b * Tc + qi) * Cc + h * HDc + lane * 2) =
        make_float2(y.x * rinv, y.y * rinv);
}

// ---------------------------------------------------------------------------
extern "C" void kernel_launch(void* const* d_in, const int* in_sizes, int n_in,
                              void* d_out, int out_size)
{
    const float* q  = (const float*)d_in[0];
    const float* Wq = (const float*)d_in[2];
    const float* bq = (const float*)d_in[3];
    const float* Wk = (const float*)d_in[4];
    const float* bk = (const float*)d_in[5];
    const float* Wv = (const float*)d_in[6];
    const float* bv = (const float*)d_in[7];
    const float* Wp = (const float*)d_in[8];
    const float* bp = (const float*)d_in[9];

    float *Qh, *Kh, *Vh, *Yb;
    cudaGetSymbolAddress((void**)&Qh, g_Qh);
    cudaGetSymbolAddress((void**)&Kh, g_Kh);
    cudaGetSymbolAddress((void**)&Vh, g_Vh);
    cudaGetSymbolAddress((void**)&Yb, g_Y);

    cudaFuncSetAttribute(attn_kernel, cudaFuncAttributeMaxDynamicSharedMemorySize,
                         (int)sizeof(AttnSmem));

    qkv_kernel<<<dim3(Cc / 128, Mr / 128, 3), 256>>>(q, Wq, bq, Wk, bk, Wv, bv, Qh, Kh, Vh);
    attn_kernel<<<dim3(Tc / QT, BHc), 256, sizeof(AttnSmem)>>>(Qh, Kh, Vh, Yb);
    sgemm_kernel<<<dim3(Cc / 128, Mr / 128), 256>>>(Yb, Wp, bp, (float*)d_out);
}

// round 11
// speedup vs baseline: 1.8724x; 1.8724x over previous
#include <cuda_runtime.h>

#define Bc 2
#define Tc 2048
#define Cc 512
#define Hc 8
#define HDc 64
#define TOPKc 64
#define BHc (Bc*Hc)
#define Mr (Bc*Tc)
#define QT 8
#define KT 128
#define CANDMAX 256

// Scratch (device globals; allocations forbidden)
__device__ float g_Qh[BHc*Tc*HDc];
__device__ float g_Kh[BHc*Tc*HDc];
__device__ float g_Vh[BHc*Tc*HDc];
__device__ float g_Y [Bc*Tc*Cc];

// ---------------------------------------------------------------------------
// helpers
// ---------------------------------------------------------------------------
__device__ __forceinline__ unsigned f2u(float f) {
    unsigned b = __float_as_uint(f);
    return b ^ ((unsigned)((int)b >> 31) | 0x80000000u);
}
__device__ __forceinline__ float u2f(unsigned u) {
    unsigned b = (u & 0x80000000u) ? (u ^ 0x80000000u) : ~u;
    return __uint_as_float(b);
}

// pick the bin containing rank `need` (scanning bins 255..0); returns
// (byte << 16) | remaining_need. Warp-collective, uses suffix scan.
__device__ __forceinline__ int radix_pick(const int* hist, int need, int lane) {
    int s = 0;
    #pragma unroll
    for (int j = 0; j < 8; j++) s += hist[255 - lane * 8 - j];
    int cum = s;
    #pragma unroll
    for (int off = 1; off < 32; off <<= 1) {
        int v = __shfl_up_sync(0xffffffffu, cum, off);
        if (lane >= off) cum += v;
    }
    unsigned bal = __ballot_sync(0xffffffffu, cum >= need);
    int selL = __ffs(bal) - 1;
    int above = __shfl_sync(0xffffffffu, cum - s, selL);
    int sneed = need - above;
    int res = 0;
    if (lane == selL) {
        int c = 0;
        #pragma unroll 1
        for (int j = 0; j < 8; j++) {
            int b = 255 - selL * 8 - j;
            int h = hist[b];
            if (c + h >= sneed) { res = (b << 16) | (sneed - c); break; }
            c += h;
        }
    }
    return __shfl_sync(0xffffffffu, res, selL);
}

// ---------------------------------------------------------------------------
// Fused QKV GEMM (round-8 exact, measured 157us): BM=BN=128, BK=8, 256 thr,
// scalar FFMA 8x8 micro, double buffer. z==2 (V): fused per-head row-norm.
// ---------------------------------------------------------------------------
__global__ void __launch_bounds__(256, 2)
qkv_kernel(const float* __restrict__ A,
           const float* __restrict__ Wq, const float* __restrict__ bq,
           const float* __restrict__ Wk, const float* __restrict__ bk,
           const float* __restrict__ Wv, const float* __restrict__ bv,
           float* __restrict__ Qh, float* __restrict__ Kh, float* __restrict__ Vh)
{
    int z = blockIdx.z;
    const float* W    = (z == 0) ? Wq : (z == 1) ? Wk : Wv;
    const float* bias = (z == 0) ? bq : (z == 1) ? bk : bv;
    float* out        = (z == 0) ? Qh : (z == 1) ? Kh : Vh;

    __shared__ float As[2][8][128];
    __shared__ float Bs[2][8][128];

    int tid = threadIdx.x;
    int bm = blockIdx.y * 128;
    int bn = blockIdx.x * 128;
    int ty = tid >> 4;
    int tx = tid & 15;

    int arow = tid >> 1;
    int akq  = (tid & 1) * 4;
    int brow = tid >> 5;
    int bcol = (tid & 31) * 4;

    const float* Ag = A + (size_t)(bm + arow) * Cc + akq;
    const float* Wg = W + (size_t)brow * Cc + bn + bcol;

    float acc[8][8];
    #pragma unroll
    for (int i = 0; i < 8; i++)
        #pragma unroll
        for (int j = 0; j < 8; j++) acc[i][j] = 0.f;

    {
        float4 av = *reinterpret_cast<const float4*>(Ag);
        float4 bv4 = *reinterpret_cast<const float4*>(Wg);
        As[0][akq + 0][arow] = av.x;
        As[0][akq + 1][arow] = av.y;
        As[0][akq + 2][arow] = av.z;
        As[0][akq + 3][arow] = av.w;
        *reinterpret_cast<float4*>(&Bs[0][brow][bcol]) = bv4;
    }
    __syncthreads();

    #pragma unroll 1
    for (int kb = 0; kb < 64; kb++) {
        int cur = kb & 1;
        float4 an, bnv;
        if (kb < 63) {
            an  = *reinterpret_cast<const float4*>(Ag + (kb + 1) * 8);
            bnv = *reinterpret_cast<const float4*>(Wg + (size_t)(kb + 1) * 8 * Cc);
        }
        #pragma unroll
        for (int k = 0; k < 8; k++) {
            float4 a0 = *reinterpret_cast<const float4*>(&As[cur][k][ty * 4]);
            float4 a1 = *reinterpret_cast<const float4*>(&As[cur][k][64 + ty * 4]);
            float4 b0 = *reinterpret_cast<const float4*>(&Bs[cur][k][tx * 4]);
            float4 b1 = *reinterpret_cast<const float4*>(&Bs[cur][k][64 + tx * 4]);
            float a[8] = {a0.x, a0.y, a0.z, a0.w, a1.x, a1.y, a1.z, a1.w};
            float b[8] = {b0.x, b0.y, b0.z, b0.w, b1.x, b1.y, b1.z, b1.w};
            #pragma unroll
            for (int i = 0; i < 8; i++)
                #pragma unroll
                for (int j = 0; j < 8; j++)
                    acc[i][j] += a[i] * b[j];
        }
        if (kb < 63) {
            int nxt = cur ^ 1;
            As[nxt][akq + 0][arow] = an.x;
            As[nxt][akq + 1][arow] = an.y;
            As[nxt][akq + 2][arow] = an.z;
            As[nxt][akq + 3][arow] = an.w;
            *reinterpret_cast<float4*>(&Bs[nxt][brow][bcol]) = bnv;
            __syncthreads();
        }
    }

    float4 bia0 = *reinterpret_cast<const float4*>(bias + bn + tx * 4);
    float4 bia1 = *reinterpret_cast<const float4*>(bias + bn + 64 + tx * 4);
    #pragma unroll
    for (int i = 0; i < 8; i++) {
        int r = (i < 4) ? (ty * 4 + i) : (64 + ty * 4 + (i - 4));
        int mrow = bm + r;
        int b = mrow >> 11;
        int t = mrow & (Tc - 1);
        float4 o0 = make_float4(acc[i][0] + bia0.x, acc[i][1] + bia0.y,
                                acc[i][2] + bia0.z, acc[i][3] + bia0.w);
        float4 o1 = make_float4(acc[i][4] + bia1.x, acc[i][5] + bia1.y,
                                acc[i][6] + bia1.z, acc[i][7] + bia1.w);
        if (z == 2) {
            float ss0 = o0.x*o0.x + o0.y*o0.y + o0.z*o0.z + o0.w*o0.w;
            float ss1 = o1.x*o1.x + o1.y*o1.y + o1.z*o1.z + o1.w*o1.w;
            #pragma unroll
            for (int off = 8; off; off >>= 1) {
                ss0 += __shfl_xor_sync(0xffffffffu, ss0, off);
                ss1 += __shfl_xor_sync(0xffffffffu, ss1, off);
            }
            float sc0 = 1.0f / fmaxf(sqrtf(ss0), 1e-12f);
            float sc1 = 1.0f / fmaxf(sqrtf(ss1), 1e-12f);
            o0.x *= sc0; o0.y *= sc0; o0.z *= sc0; o0.w *= sc0;
            o1.x *= sc1; o1.y *= sc1; o1.z *= sc1; o1.w *= sc1;
        }
        int n0 = bn + tx * 4;       int h0 = n0 >> 6, d0 = n0 & 63;
        int n1 = bn + 64 + tx * 4;  int h1 = n1 >> 6, d1 = n1 & 63;
        *reinterpret_cast<float4*>(out + ((size_t)((b * Hc + h0) * Tc + t) << 6) + d0) = o0;
        *reinterpret_cast<float4*>(out + ((size_t)((b * Hc + h1) * Tc + t) << 6) + d1) = o1;
    }
}

// ---------------------------------------------------------------------------
// Output projection GEMM (row-major out), scalar FFMA (round-8 exact).
// ---------------------------------------------------------------------------
__global__ void __launch_bounds__(256, 2)
sgemm_kernel(const float* __restrict__ A, const float* __restrict__ W,
             const float* __restrict__ bias, float* __restrict__ out)
{
    __shared__ float As[2][8][128];
    __shared__ float Bs[2][8][128];

    int tid = threadIdx.x;
    int bm = blockIdx.y * 128;
    int bn = blockIdx.x * 128;
    int ty = tid >> 4;
    int tx = tid & 15;

    int arow = tid >> 1;
    int akq  = (tid & 1) * 4;
    int brow = tid >> 5;
    int bcol = (tid & 31) * 4;

    const float* Ag = A + (size_t)(bm + arow) * Cc + akq;
    const float* Wg = W + (size_t)brow * Cc + bn + bcol;

    float acc[8][8];
    #pragma unroll
    for (int i = 0; i < 8; i++)
        #pragma unroll
        for (int j = 0; j < 8; j++) acc[i][j] = 0.f;

    {
        float4 av = *reinterpret_cast<const float4*>(Ag);
        float4 bv4 = *reinterpret_cast<const float4*>(Wg);
        As[0][akq + 0][arow] = av.x;
        As[0][akq + 1][arow] = av.y;
        As[0][akq + 2][arow] = av.z;
        As[0][akq + 3][arow] = av.w;
        *reinterpret_cast<float4*>(&Bs[0][brow][bcol]) = bv4;
    }
    __syncthreads();

    #pragma unroll 1
    for (int kb = 0; kb < 64; kb++) {
        int cur = kb & 1;
        float4 an, bnv;
        if (kb < 63) {
            an  = *reinterpret_cast<const float4*>(Ag + (kb + 1) * 8);
            bnv = *reinterpret_cast<const float4*>(Wg + (size_t)(kb + 1) * 8 * Cc);
        }
        #pragma unroll
        for (int k = 0; k < 8; k++) {
            float4 a0 = *reinterpret_cast<const float4*>(&As[cur][k][ty * 4]);
            float4 a1 = *reinterpret_cast<const float4*>(&As[cur][k][64 + ty * 4]);
            float4 b0 = *reinterpret_cast<const float4*>(&Bs[cur][k][tx * 4]);
            float4 b1 = *reinterpret_cast<const float4*>(&Bs[cur][k][64 + tx * 4]);
            float a[8] = {a0.x, a0.y, a0.z, a0.w, a1.x, a1.y, a1.z, a1.w};
            float b[8] = {b0.x, b0.y, b0.z, b0.w, b1.x, b1.y, b1.z, b1.w};
            #pragma unroll
            for (int i = 0; i < 8; i++)
                #pragma unroll
                for (int j = 0; j < 8; j++)
                    acc[i][j] += a[i] * b[j];
        }
        if (kb < 63) {
            int nxt = cur ^ 1;
            As[nxt][akq + 0][arow] = an.x;
            As[nxt][akq + 1][arow] = an.y;
            As[nxt][akq + 2][arow] = an.z;
            As[nxt][akq + 3][arow] = an.w;
            *reinterpret_cast<float4*>(&Bs[nxt][brow][bcol]) = bnv;
            __syncthreads();
        }
    }

    float4 bia0 = *reinterpret_cast<const float4*>(bias + bn + tx * 4);
    float4 bia1 = *reinterpret_cast<const float4*>(bias + bn + 64 + tx * 4);
    #pragma unroll
    for (int i = 0; i < 8; i++) {
        int r = (i < 4) ? (ty * 4 + i) : (64 + ty * 4 + (i - 4));
        int mrow = bm + r;
        float4 o0 = make_float4(acc[i][0] + bia0.x, acc[i][1] + bia0.y,
                                acc[i][2] + bia0.z, acc[i][3] + bia0.w);
        float4 o1 = make_float4(acc[i][4] + bia1.x, acc[i][5] + bia1.y,
                                acc[i][6] + bia1.z, acc[i][7] + bia1.w);
        *reinterpret_cast<float4*>(out + (size_t)mrow * Cc + bn + tx * 4) = o0;
        *reinterpret_cast<float4*>(out + (size_t)mrow * Cc + bn + 64 + tx * 4) = o1;
    }
}

// ---------------------------------------------------------------------------
// Attention: round-8 exact EXCEPT radix passes 2-4 run over a compacted
// candidate list (keys whose top byte == pass-1 bin; count typically <=256)
// instead of the full array. Identical counts -> identical threshold.
// Fallback to full sweeps if candidates overflow CANDMAX.
// ---------------------------------------------------------------------------
struct AttnSmem {
    float qs[QT][HDc];                 // 2 KB
    float kt[KT][68];                  // 34.8 KB
    unsigned su[QT][Tc];               // 64 KB scores / probs
    union RowSel {
        int hist[256];
        unsigned short sidx[512];
    } sel[QT];                         // 8 KB
    unsigned short cand[QT][CANDMAX];  // 4 KB
};

__global__ void __launch_bounds__(256, 2)
attn_kernel(const float* __restrict__ Q, const float* __restrict__ K,
            const float* __restrict__ V, float* __restrict__ Y)
{
    extern __shared__ unsigned char raw[];
    AttnSmem* S = reinterpret_cast<AttnSmem*>(raw);

    int tid  = threadIdx.x;
    int warp = tid >> 5;
    int lane = tid & 31;

    int bh = blockIdx.y;
    int qbase = ((int)gridDim.x - 1 - (int)blockIdx.x) * QT;  // long rows first
    int n_max = qbase + QT;

    const float* Kb = K + (size_t)bh * Tc * HDc;
    const float* Vb = V + (size_t)bh * Tc * HDc;

    if (tid < 128) {
        int r = tid >> 4, i = tid & 15;
        reinterpret_cast<float4*>(S->qs[r])[i] =
            reinterpret_cast<const float4*>(Q + ((size_t)bh * Tc + qbase + r) * HDc)[i];
    }

    // score-phase mapping: 4 rows x quarter keys per warp
    int quarter = warp >> 1;
    int rgrp = (warp & 1) * 4;
    int kqoff = quarter * 32 + lane;
    const float4* q40 = reinterpret_cast<const float4*>(S->qs[rgrp + 0]);
    const float4* q41 = reinterpret_cast<const float4*>(S->qs[rgrp + 1]);
    const float4* q42 = reinterpret_cast<const float4*>(S->qs[rgrp + 2]);
    const float4* q43 = reinterpret_cast<const float4*>(S->qs[rgrp + 3]);

    int ldrow = tid >> 4;
    int lddq  = (tid & 15) * 4;

    int ntiles = (n_max + KT - 1) / KT;

    // prologue: tile 0 -> registers
    float4 rv[8];
    #pragma unroll
    for (int i = 0; i < 8; i++)
        rv[i] = *reinterpret_cast<const float4*>(Kb + (size_t)(ldrow + 16 * i) * HDc + lddq);

    #pragma unroll 1
    for (int t = 0; t < ntiles; t++) {
        __syncthreads();
        #pragma unroll
        for (int i = 0; i < 8; i++)
            *reinterpret_cast<float4*>(&S->kt[ldrow + 16 * i][lddq]) = rv[i];
        __syncthreads();

        if (t + 1 < ntiles) {
            int t0n = (t + 1) * KT;
            #pragma unroll
            for (int i = 0; i < 8; i++)
                rv[i] = *reinterpret_cast<const float4*>(
                            Kb + (size_t)(t0n + ldrow + 16 * i) * HDc + lddq);
        }

        float a0 = 0.f, a1 = 0.f, a2 = 0.f, a3 = 0.f;
        #pragma unroll
        for (int i = 0; i < 16; i++) {
            float4 kv = *reinterpret_cast<const float4*>(&S->kt[kqoff][i * 4]);
            float4 qa = q40[i], qb = q41[i], qc = q42[i], qd = q43[i];
            a0 += qa.x * kv.x + qa.y * kv.y + qa.z * kv.z + qa.w * kv.w;
            a1 += qb.x * kv.x + qb.y * kv.y + qb.z * kv.z + qb.w * kv.w;
            a2 += qc.x * kv.x + qc.y * kv.y + qc.z * kv.z + qc.w * kv.w;
            a3 += qd.x * kv.x + qd.y * kv.y + qd.z * kv.z + qd.w * kv.w;
        }
        int k = t * KT + kqoff;
        if (k <= qbase + rgrp + 0) S->su[rgrp + 0][k] = f2u(a0 * 0.125f);
        if (k <= qbase + rgrp + 1) S->su[rgrp + 1][k] = f2u(a1 * 0.125f);
        if (k <= qbase + rgrp + 2) S->su[rgrp + 2][k] = f2u(a2 * 0.125f);
        if (k <= qbase + rgrp + 3) S->su[rgrp + 3][k] = f2u(a3 * 0.125f);
    }
    __syncthreads();   // all scores visible; switch to warp<->row mapping

    int row = warp;
    int qi = qbase + row;
    int n = qi + 1;
    unsigned* su = S->su[row];
    int* hist = S->sel[row].hist;

    // ---- exact rank-64 threshold: byte radix with candidate compaction
    unsigned thrU = 0u;
    if (n > TOPKc) {
        // pass 1: top byte over full array (colliding atomics — measured fast)
        #pragma unroll
        for (int b = lane; b < 256; b += 32) hist[b] = 0;
        __syncwarp();
        for (int k = lane; k < n; k += 32)
            atomicAdd(&hist[su[k] >> 24], 1);
        __syncwarp();
        int res = radix_pick(hist, TOPKc, lane);
        unsigned b1 = (unsigned)(res >> 16);
        int need = res & 0xffff;
        unsigned pref = b1 << 24;

        // candidate compaction: keys with top byte == b1 (ordered, no atomics)
        unsigned short* cd = S->cand[row];
        int c = 0;
        #pragma unroll 1
        for (int k0 = 0; k0 < n; k0 += 32) {
            int k = k0 + lane;
            bool is = (k < n) && ((su[k] >> 24) == b1);
            unsigned bal = __ballot_sync(0xffffffffu, is);
            if (is) {
                int pos = c + __popc(bal & ((1u << lane) - 1u));
                if (pos < CANDMAX) cd[pos] = (unsigned short)k;
            }
            c += __popc(bal);
        }

        if (c <= CANDMAX) {
            // passes 2-4 over candidates only
            #pragma unroll 1
            for (int by = 2; by >= 0; --by) {
                int sh = by * 8;
                #pragma unroll
                for (int b = lane; b < 256; b += 32) hist[b] = 0;
                __syncwarp();
                unsigned hp = pref >> (sh + 8);
                #pragma unroll 1
                for (int j = lane; j < c; j += 32) {
                    unsigned u = su[cd[j]];
                    if ((u >> (sh + 8)) == hp)
                        atomicAdd(&hist[(u >> sh) & 255u], 1);
                }
                __syncwarp();
                int r2 = radix_pick(hist, need, lane);
                pref |= (unsigned)(r2 >> 16) << sh;
                need = r2 & 0xffff;
            }
        } else {
            // fallback: full-array passes (round-8 form)
            #pragma unroll 1
            for (int by = 2; by >= 0; --by) {
                int sh = by * 8;
                #pragma unroll
                for (int b = lane; b < 256; b += 32) hist[b] = 0;
                __syncwarp();
                unsigned hp = pref >> (sh + 8);
                for (int k = lane; k < n; k += 32) {
                    unsigned u = su[k];
                    if ((u >> (sh + 8)) == hp)
                        atomicAdd(&hist[(u >> sh) & 255u], 1);
                }
                __syncwarp();
                int r2 = radix_pick(hist, need, lane);
                pref |= (unsigned)(r2 >> 16) << sh;
                need = r2 & 0xffff;
            }
        }
        thrU = pref;
    }
    __syncwarp();

    // ---- ballot compaction (ordered) + row max
    unsigned short* sidx = S->sel[row].sidx;
    int m = 0; unsigned umax = 0u;
    #pragma unroll 1
    for (int k0 = 0; k0 < n; k0 += 32) {
        int k = k0 + lane;
        bool a = k < n;
        unsigned u = a ? su[k] : 0u;
        umax = max(umax, u);
        bool keep = a && (u >= thrU);
        unsigned bal = __ballot_sync(0xffffffffu, keep);
        if (keep) {
            int pos = m + __popc(bal & ((1u << lane) - 1u));
            if (pos < 512) sidx[pos] = (unsigned short)k;
        }
        m += __popc(bal);
    }
    if (m > 512) m = 512;
    #pragma unroll
    for (int off = 16; off; off >>= 1)
        umax = max(umax, __shfl_xor_sync(0xffffffffu, umax, off));

    // ---- softmax over survivors (probs overwrite su in place)
    float maxf = u2f(umax);
    float lsum = 0.f;
    for (int j = lane; j < m; j += 32) {
        int k = sidx[j];
        float p = __expf(u2f(su[k]) - maxf);
        su[k] = __float_as_uint(p);
        lsum += p;
    }
    __syncwarp();
    #pragma unroll
    for (int off = 16; off; off >>= 1) lsum += __shfl_xor_sync(0xffffffffu, lsum, off);
    float rinv = 1.0f / lsum;

    // ---- sparse PV (round-8 form)
    const float2* V2 = reinterpret_cast<const float2*>(Vb);
    float2 y = make_float2(0.f, 0.f);
    int j = 0;
    for (; j + 4 <= m; j += 4) {
        int k0 = sidx[j + 0], k1 = sidx[j + 1], k2 = sidx[j + 2], k3 = sidx[j + 3];
        float p0 = __uint_as_float(su[k0]);
        float p1 = __uint_as_float(su[k1]);
        float p2 = __uint_as_float(su[k2]);
        float p3 = __uint_as_float(su[k3]);
        float2 v0 = V2[(size_t)k0 * 32 + lane];
        float2 v1 = V2[(size_t)k1 * 32 + lane];
        float2 v2 = V2[(size_t)k2 * 32 + lane];
        float2 v3 = V2[(size_t)k3 * 32 + lane];
        y.x += p0 * v0.x + p1 * v1.x + p2 * v2.x + p3 * v3.x;
        y.y += p0 * v0.y + p1 * v1.y + p2 * v2.y + p3 * v3.y;
    }
    for (; j < m; j++) {
        int k = sidx[j];
        float p = __uint_as_float(su[k]);
        float2 v = V2[(size_t)k * 32 + lane];
        y.x += p * v.x; y.y += p * v.y;
    }
    int b = bh >> 3, h = bh & 7;
    *reinterpret_cast<float2*>(Y + (size_t)(b * Tc + qi) * Cc + h * HDc + lane * 2) =
        make_float2(y.x * rinv, y.y * rinv);
}

// ---------------------------------------------------------------------------
extern "C" void kernel_launch(void* const* d_in, const int* in_sizes, int n_in,
                              void* d_out, int out_size)
{
    const float* q  = (const float*)d_in[0];
    const float* Wq = (const float*)d_in[2];
    const float* bq = (const float*)d_in[3];
    const float* Wk = (const float*)d_in[4];
    const float* bk = (const float*)d_in[5];
    const float* Wv = (const float*)d_in[6];
    const float* bv = (const float*)d_in[7];
    const float* Wp = (const float*)d_in[8];
    const float* bp = (const float*)d_in[9];

    float *Qh, *Kh, *Vh, *Yb;
    cudaGetSymbolAddress((void**)&Qh, g_Qh);
    cudaGetSymbolAddress((void**)&Kh, g_Kh);
    cudaGetSymbolAddress((void**)&Vh, g_Vh);
    cudaGetSymbolAddress((void**)&Yb, g_Y);

    cudaFuncSetAttribute(attn_kernel, cudaFuncAttributeMaxDynamicSharedMemorySize,
                         (int)sizeof(AttnSmem));

    qkv_kernel<<<dim3(Cc / 128, Mr / 128, 3), 256>>>(q, Wq, bq, Wk, bk, Wv, bv, Qh, Kh, Vh);
    attn_kernel<<<dim3(Tc / QT, BHc), 256, sizeof(AttnSmem)>>>(Qh, Kh, Vh, Yb);
    sgemm_kernel<<<dim3(Cc / 128, Mr / 128), 256>>>(Yb, Wp, bp, (float*)d_out);
}

// round 12
// speedup vs baseline: 1.8998x; 1.0146x over previous
#include <cuda_runtime.h>

#define Bc 2
#define Tc 2048
#define Cc 512
#define Hc 8
#define HDc 64
#define TOPKc 64
#define BHc (Bc*Hc)
#define Mr (Bc*Tc)
#define QT 8
#define KT 128

// Scratch (device globals; allocations forbidden)
__device__ float g_Qh[BHc*Tc*HDc];
__device__ float g_Kh[BHc*Tc*HDc];
__device__ float g_Vh[BHc*Tc*HDc];
__device__ float g_Y [Bc*Tc*Cc];
__device__ unsigned g_SU[(size_t)BHc*Tc*Tc];   // scores as ordered uints (256 MB)

// ---------------------------------------------------------------------------
// helpers
// ---------------------------------------------------------------------------
__device__ __forceinline__ unsigned f2u(float f) {
    unsigned b = __float_as_uint(f);
    return b ^ ((unsigned)((int)b >> 31) | 0x80000000u);
}
__device__ __forceinline__ float u2f(unsigned u) {
    unsigned b = (u & 0x80000000u) ? (u ^ 0x80000000u) : ~u;
    return __uint_as_float(b);
}

// ---------------------------------------------------------------------------
// Fused QKV GEMM (round-8 exact, measured 157us): BM=BN=128, BK=8, 256 thr,
// scalar FFMA 8x8 micro, double buffer. z==2 (V): fused per-head row-norm.
// ---------------------------------------------------------------------------
__global__ void __launch_bounds__(256, 2)
qkv_kernel(const float* __restrict__ A,
           const float* __restrict__ Wq, const float* __restrict__ bq,
           const float* __restrict__ Wk, const float* __restrict__ bk,
           const float* __restrict__ Wv, const float* __restrict__ bv,
           float* __restrict__ Qh, float* __restrict__ Kh, float* __restrict__ Vh)
{
    int z = blockIdx.z;
    const float* W    = (z == 0) ? Wq : (z == 1) ? Wk : Wv;
    const float* bias = (z == 0) ? bq : (z == 1) ? bk : bv;
    float* out        = (z == 0) ? Qh : (z == 1) ? Kh : Vh;

    __shared__ float As[2][8][128];
    __shared__ float Bs[2][8][128];

    int tid = threadIdx.x;
    int bm = blockIdx.y * 128;
    int bn = blockIdx.x * 128;
    int ty = tid >> 4;
    int tx = tid & 15;

    int arow = tid >> 1;
    int akq  = (tid & 1) * 4;
    int brow = tid >> 5;
    int bcol = (tid & 31) * 4;

    const float* Ag = A + (size_t)(bm + arow) * Cc + akq;
    const float* Wg = W + (size_t)brow * Cc + bn + bcol;

    float acc[8][8];
    #pragma unroll
    for (int i = 0; i < 8; i++)
        #pragma unroll
        for (int j = 0; j < 8; j++) acc[i][j] = 0.f;

    {
        float4 av = *reinterpret_cast<const float4*>(Ag);
        float4 bv4 = *reinterpret_cast<const float4*>(Wg);
        As[0][akq + 0][arow] = av.x;
        As[0][akq + 1][arow] = av.y;
        As[0][akq + 2][arow] = av.z;
        As[0][akq + 3][arow] = av.w;
        *reinterpret_cast<float4*>(&Bs[0][brow][bcol]) = bv4;
    }
    __syncthreads();

    #pragma unroll 1
    for (int kb = 0; kb < 64; kb++) {
        int cur = kb & 1;
        float4 an, bnv;
        if (kb < 63) {
            an  = *reinterpret_cast<const float4*>(Ag + (kb + 1) * 8);
            bnv = *reinterpret_cast<const float4*>(Wg + (size_t)(kb + 1) * 8 * Cc);
        }
        #pragma unroll
        for (int k = 0; k < 8; k++) {
            float4 a0 = *reinterpret_cast<const float4*>(&As[cur][k][ty * 4]);
            float4 a1 = *reinterpret_cast<const float4*>(&As[cur][k][64 + ty * 4]);
            float4 b0 = *reinterpret_cast<const float4*>(&Bs[cur][k][tx * 4]);
            float4 b1 = *reinterpret_cast<const float4*>(&Bs[cur][k][64 + tx * 4]);
            float a[8] = {a0.x, a0.y, a0.z, a0.w, a1.x, a1.y, a1.z, a1.w};
            float b[8] = {b0.x, b0.y, b0.z, b0.w, b1.x, b1.y, b1.z, b1.w};
            #pragma unroll
            for (int i = 0; i < 8; i++)
                #pragma unroll
                for (int j = 0; j < 8; j++)
                    acc[i][j] += a[i] * b[j];
        }
        if (kb < 63) {
            int nxt = cur ^ 1;
            As[nxt][akq + 0][arow] = an.x;
            As[nxt][akq + 1][arow] = an.y;
            As[nxt][akq + 2][arow] = an.z;
            As[nxt][akq + 3][arow] = an.w;
            *reinterpret_cast<float4*>(&Bs[nxt][brow][bcol]) = bnv;
            __syncthreads();
        }
    }

    float4 bia0 = *reinterpret_cast<const float4*>(bias + bn + tx * 4);
    float4 bia1 = *reinterpret_cast<const float4*>(bias + bn + 64 + tx * 4);
    #pragma unroll
    for (int i = 0; i < 8; i++) {
        int r = (i < 4) ? (ty * 4 + i) : (64 + ty * 4 + (i - 4));
        int mrow = bm + r;
        int b = mrow >> 11;
        int t = mrow & (Tc - 1);
        float4 o0 = make_float4(acc[i][0] + bia0.x, acc[i][1] + bia0.y,
                                acc[i][2] + bia0.z, acc[i][3] + bia0.w);
        float4 o1 = make_float4(acc[i][4] + bia1.x, acc[i][5] + bia1.y,
                                acc[i][6] + bia1.z, acc[i][7] + bia1.w);
        if (z == 2) {
            float ss0 = o0.x*o0.x + o0.y*o0.y + o0.z*o0.z + o0.w*o0.w;
            float ss1 = o1.x*o1.x + o1.y*o1.y + o1.z*o1.z + o1.w*o1.w;
            #pragma unroll
            for (int off = 8; off; off >>= 1) {
                ss0 += __shfl_xor_sync(0xffffffffu, ss0, off);
                ss1 += __shfl_xor_sync(0xffffffffu, ss1, off);
            }
            float sc0 = 1.0f / fmaxf(sqrtf(ss0), 1e-12f);
            float sc1 = 1.0f / fmaxf(sqrtf(ss1), 1e-12f);
            o0.x *= sc0; o0.y *= sc0; o0.z *= sc0; o0.w *= sc0;
            o1.x *= sc1; o1.y *= sc1; o1.z *= sc1; o1.w *= sc1;
        }
        int n0 = bn + tx * 4;       int h0 = n0 >> 6, d0 = n0 & 63;
        int n1 = bn + 64 + tx * 4;  int h1 = n1 >> 6, d1 = n1 & 63;
        *reinterpret_cast<float4*>(out + ((size_t)((b * Hc + h0) * Tc + t) << 6) + d0) = o0;
        *reinterpret_cast<float4*>(out + ((size_t)((b * Hc + h1) * Tc + t) << 6) + d1) = o1;
    }
}

// ---------------------------------------------------------------------------
// Output projection GEMM (row-major out), scalar FFMA (round-8 exact).
// ---------------------------------------------------------------------------
__global__ void __launch_bounds__(256, 2)
sgemm_kernel(const float* __restrict__ A, const float* __restrict__ W,
             const float* __restrict__ bias, float* __restrict__ out)
{
    __shared__ float As[2][8][128];
    __shared__ float Bs[2][8][128];

    int tid = threadIdx.x;
    int bm = blockIdx.y * 128;
    int bn = blockIdx.x * 128;
    int ty = tid >> 4;
    int tx = tid & 15;

    int arow = tid >> 1;
    int akq  = (tid & 1) * 4;
    int brow = tid >> 5;
    int bcol = (tid & 31) * 4;

    const float* Ag = A + (size_t)(bm + arow) * Cc + akq;
    const float* Wg = W + (size_t)brow * Cc + bn + bcol;

    float acc[8][8];
    #pragma unroll
    for (int i = 0; i < 8; i++)
        #pragma unroll
        for (int j = 0; j < 8; j++) acc[i][j] = 0.f;

    {
        float4 av = *reinterpret_cast<const float4*>(Ag);
        float4 bv4 = *reinterpret_cast<const float4*>(Wg);
        As[0][akq + 0][arow] = av.x;
        As[0][akq + 1][arow] = av.y;
        As[0][akq + 2][arow] = av.z;
        As[0][akq + 3][arow] = av.w;
        *reinterpret_cast<float4*>(&Bs[0][brow][bcol]) = bv4;
    }
    __syncthreads();

    #pragma unroll 1
    for (int kb = 0; kb < 64; kb++) {
        int cur = kb & 1;
        float4 an, bnv;
        if (kb < 63) {
            an  = *reinterpret_cast<const float4*>(Ag + (kb + 1) * 8);
            bnv = *reinterpret_cast<const float4*>(Wg + (size_t)(kb + 1) * 8 * Cc);
        }
        #pragma unroll
        for (int k = 0; k < 8; k++) {
            float4 a0 = *reinterpret_cast<const float4*>(&As[cur][k][ty * 4]);
            float4 a1 = *reinterpret_cast<const float4*>(&As[cur][k][64 + ty * 4]);
            float4 b0 = *reinterpret_cast<const float4*>(&Bs[cur][k][tx * 4]);
            float4 b1 = *reinterpret_cast<const float4*>(&Bs[cur][k][64 + tx * 4]);
            float a[8] = {a0.x, a0.y, a0.z, a0.w, a1.x, a1.y, a1.z, a1.w};
            float b[8] = {b0.x, b0.y, b0.z, b0.w, b1.x, b1.y, b1.z, b1.w};
            #pragma unroll
            for (int i = 0; i < 8; i++)
                #pragma unroll
                for (int j = 0; j < 8; j++)
                    acc[i][j] += a[i] * b[j];
        }
        if (kb < 63) {
            int nxt = cur ^ 1;
            As[nxt][akq + 0][arow] = an.x;
            As[nxt][akq + 1][arow] = an.y;
            As[nxt][akq + 2][arow] = an.z;
            As[nxt][akq + 3][arow] = an.w;
            *reinterpret_cast<float4*>(&Bs[nxt][brow][bcol]) = bnv;
            __syncthreads();
        }
    }

    float4 bia0 = *reinterpret_cast<const float4*>(bias + bn + tx * 4);
    float4 bia1 = *reinterpret_cast<const float4*>(bias + bn + 64 + tx * 4);
    #pragma unroll
    for (int i = 0; i < 8; i++) {
        int r = (i < 4) ? (ty * 4 + i) : (64 + ty * 4 + (i - 4));
        int mrow = bm + r;
        float4 o0 = make_float4(acc[i][0] + bia0.x, acc[i][1] + bia0.y,
                                acc[i][2] + bia0.z, acc[i][3] + bia0.w);
        float4 o1 = make_float4(acc[i][4] + bia1.x, acc[i][5] + bia1.y,
                                acc[i][6] + bia1.z, acc[i][7] + bia1.w);
        *reinterpret_cast<float4*>(out + (size_t)mrow * Cc + bn + tx * 4) = o0;
        *reinterpret_cast<float4*>(out + (size_t)mrow * Cc + bn + 64 + tx * 4) = o1;
    }
}

// ---------------------------------------------------------------------------
// Attention: round-8 logic, but su lives in GLOBAL scratch (L2-resident) and
// softmax probs go to a dense smem buffer. SMEM 60KB -> 3 blocks/SM
// (24 warps, 1.5x occupancy). No register prefetch (reg cap 84).
// ---------------------------------------------------------------------------
struct AttnSmem {
    float qs[QT][HDc];                 // 2 KB
    float kt[KT][68];                  // 34.8 KB
    union RowSel {
        int hist[256];
        unsigned short sidx[512];
    } sel[QT];                         // 8 KB
    float prob[QT][512];               // 16 KB dense softmax numerators
};

__global__ void __launch_bounds__(256, 3)
attn_kernel(const float* __restrict__ Q, const float* __restrict__ K,
            const float* __restrict__ V, float* __restrict__ Y,
            unsigned* __restrict__ gsu)
{
    extern __shared__ unsigned char raw[];
    AttnSmem* S = reinterpret_cast<AttnSmem*>(raw);

    int tid  = threadIdx.x;
    int warp = tid >> 5;
    int lane = tid & 31;

    int bh = blockIdx.y;
    int qbase = ((int)gridDim.x - 1 - (int)blockIdx.x) * QT;  // long rows first
    int n_max = qbase + QT;

    const float* Kb = K + (size_t)bh * Tc * HDc;
    const float* Vb = V + (size_t)bh * Tc * HDc;
    unsigned* su_base = gsu + (size_t)(bh * Tc + qbase) * Tc;  // row r at su_base + r*Tc

    if (tid < 128) {
        int r = tid >> 4, i = tid & 15;
        reinterpret_cast<float4*>(S->qs[r])[i] =
            reinterpret_cast<const float4*>(Q + ((size_t)bh * Tc + qbase + r) * HDc)[i];
    }

    // score-phase mapping: 4 rows x quarter keys per warp
    int quarter = warp >> 1;
    int rgrp = (warp & 1) * 4;
    int kqoff = quarter * 32 + lane;
    const float4* q40 = reinterpret_cast<const float4*>(S->qs[rgrp + 0]);
    const float4* q41 = reinterpret_cast<const float4*>(S->qs[rgrp + 1]);
    const float4* q42 = reinterpret_cast<const float4*>(S->qs[rgrp + 2]);
    const float4* q43 = reinterpret_cast<const float4*>(S->qs[rgrp + 3]);

    int ldrow = tid >> 4;
    int lddq  = (tid & 15) * 4;

    int ntiles = (n_max + KT - 1) / KT;

    #pragma unroll 1
    for (int t = 0; t < ntiles; t++) {
        int t0 = t * KT;
        __syncthreads();
        #pragma unroll
        for (int i = 0; i < 8; i++) {
            float4 v = *reinterpret_cast<const float4*>(
                Kb + (size_t)(t0 + ldrow + 16 * i) * HDc + lddq);
            *reinterpret_cast<float4*>(&S->kt[ldrow + 16 * i][lddq]) = v;
        }
        __syncthreads();

        float a0 = 0.f, a1 = 0.f, a2 = 0.f, a3 = 0.f;
        #pragma unroll
        for (int i = 0; i < 16; i++) {
            float4 kv = *reinterpret_cast<const float4*>(&S->kt[kqoff][i * 4]);
            float4 qa = q40[i], qb = q41[i], qc = q42[i], qd = q43[i];
            a0 += qa.x * kv.x + qa.y * kv.y + qa.z * kv.z + qa.w * kv.w;
            a1 += qb.x * kv.x + qb.y * kv.y + qb.z * kv.z + qb.w * kv.w;
            a2 += qc.x * kv.x + qc.y * kv.y + qc.z * kv.z + qc.w * kv.w;
            a3 += qd.x * kv.x + qd.y * kv.y + qd.z * kv.z + qd.w * kv.w;
        }
        int k = t0 + kqoff;
        if (k <= qbase + rgrp + 0) su_base[(size_t)(rgrp + 0) * Tc + k] = f2u(a0 * 0.125f);
        if (k <= qbase + rgrp + 1) su_base[(size_t)(rgrp + 1) * Tc + k] = f2u(a1 * 0.125f);
        if (k <= qbase + rgrp + 2) su_base[(size_t)(rgrp + 2) * Tc + k] = f2u(a2 * 0.125f);
        if (k <= qbase + rgrp + 3) su_base[(size_t)(rgrp + 3) * Tc + k] = f2u(a3 * 0.125f);
    }
    __syncthreads();   // global writes visible block-wide; warp<->row mapping

    int row = warp;
    int qi = qbase + row;
    int n = qi + 1;
    unsigned* su = su_base + (size_t)row * Tc;
    int* hist = S->sel[row].hist;

    // ---- exact rank-64 threshold: 4-pass byte radix (r8 atomics form)
    unsigned thrU = 0u;
    if (n > TOPKc) {
        unsigned pref = 0u; int need = TOPKc;
        #pragma unroll 1
        for (int by = 3; by >= 0; --by) {
            int sh = by * 8;
            #pragma unroll
            for (int b = lane; b < 256; b += 32) hist[b] = 0;
            __syncwarp();
            if (by == 3) {
                for (int k = lane; k < n; k += 32)
                    atomicAdd(&hist[su[k] >> 24], 1);
            } else {
                unsigned hp = pref >> (sh + 8);
                for (int k = lane; k < n; k += 32) {
                    unsigned u = su[k];
                    if ((u >> (sh + 8)) == hp)
                        atomicAdd(&hist[(u >> sh) & 255u], 1);
                }
            }
            __syncwarp();
            int s = 0;
            #pragma unroll
            for (int j = 0; j < 8; j++) s += hist[255 - lane * 8 - j];
            int cum = s;
            #pragma unroll
            for (int off = 1; off < 32; off <<= 1) {
                int v = __shfl_up_sync(0xffffffffu, cum, off);
                if (lane >= off) cum += v;
            }
            unsigned bal = __ballot_sync(0xffffffffu, cum >= need);
            int selL = __ffs(bal) - 1;
            int above = __shfl_sync(0xffffffffu, cum - s, selL);
            int sneed = need - above;
            int res = 0;
            if (lane == selL) {
                int c = 0;
                #pragma unroll 1
                for (int j = 0; j < 8; j++) {
                    int b = 255 - selL * 8 - j;
                    int h = hist[b];
                    if (c + h >= sneed) { res = (b << 16) | (sneed - c); break; }
                    c += h;
                }
            }
            res = __shfl_sync(0xffffffffu, res, selL);
            pref |= (unsigned)(res >> 16) << sh;
            need = res & 0xffff;
        }
        thrU = pref;
    }
    __syncwarp();

    // ---- ballot compaction (ordered) + row max
    unsigned short* sidx = S->sel[row].sidx;
    int m = 0; unsigned umax = 0u;
    #pragma unroll 1
    for (int k0 = 0; k0 < n; k0 += 32) {
        int k = k0 + lane;
        bool a = k < n;
        unsigned u = a ? su[k] : 0u;
        umax = max(umax, u);
        bool keep = a && (u >= thrU);
        unsigned bal = __ballot_sync(0xffffffffu, keep);
        if (keep) {
            int pos = m + __popc(bal & ((1u << lane) - 1u));
            if (pos < 512) sidx[pos] = (unsigned short)k;
        }
        m += __popc(bal);
    }
    if (m > 512) m = 512;
    #pragma unroll
    for (int off = 16; off; off >>= 1)
        umax = max(umax, __shfl_xor_sync(0xffffffffu, umax, off));

    // ---- softmax over survivors -> dense prob buffer
    float maxf = u2f(umax);
    float lsum = 0.f;
    for (int j = lane; j < m; j += 32) {
        int k = sidx[j];
        float p = __expf(u2f(su[k]) - maxf);
        S->prob[row][j] = p;
        lsum += p;
    }
    __syncwarp();
    #pragma unroll
    for (int off = 16; off; off >>= 1) lsum += __shfl_xor_sync(0xffffffffu, lsum, off);
    float rinv = 1.0f / lsum;

    // ---- sparse PV (dense probs, r8 access pattern on V)
    const float2* V2 = reinterpret_cast<const float2*>(Vb);
    const float* pr = S->prob[row];
    float2 y = make_float2(0.f, 0.f);
    int j = 0;
    for (; j + 4 <= m; j += 4) {
        int k0 = sidx[j + 0], k1 = sidx[j + 1], k2 = sidx[j + 2], k3 = sidx[j + 3];
        float p0 = pr[j + 0], p1 = pr[j + 1], p2 = pr[j + 2], p3 = pr[j + 3];
        float2 v0 = V2[(size_t)k0 * 32 + lane];
        float2 v1 = V2[(size_t)k1 * 32 + lane];
        float2 v2 = V2[(size_t)k2 * 32 + lane];
        float2 v3 = V2[(size_t)k3 * 32 + lane];
        y.x += p0 * v0.x + p1 * v1.x + p2 * v2.x + p3 * v3.x;
        y.y += p0 * v0.y + p1 * v1.y + p2 * v2.y + p3 * v3.y;
    }
    for (; j < m; j++) {
        int k = sidx[j];
        float p = pr[j];
        float2 v = V2[(size_t)k * 32 + lane];
        y.x += p * v.x; y.y += p * v.y;
    }
    int b = bh >> 3, h = bh & 7;
    *reinterpret_cast<float2*>(Y + (size_t)(b * Tc + qi) * Cc + h * HDc + lane * 2) =
        make_float2(y.x * rinv, y.y * rinv);
}

// ---------------------------------------------------------------------------
extern "C" void kernel_launch(void* const* d_in, const int* in_sizes, int n_in,
                              void* d_out, int out_size)
{
    const float* q  = (const float*)d_in[0];
    const float* Wq = (const float*)d_in[2];
    const float* bq = (const float*)d_in[3];
    const float* Wk = (const float*)d_in[4];
    const float* bk = (const float*)d_in[5];
    const float* Wv = (const float*)d_in[6];
    const float* bv = (const float*)d_in[7];
    const float* Wp = (const float*)d_in[8];
    const float* bp = (const float*)d_in[9];

    float *Qh, *Kh, *Vh, *Yb;
    unsigned* SU;
    cudaGetSymbolAddress((void**)&Qh, g_Qh);
    cudaGetSymbolAddress((void**)&Kh, g_Kh);
    cudaGetSymbolAddress((void**)&Vh, g_Vh);
    cudaGetSymbolAddress((void**)&Yb, g_Y);
    cudaGetSymbolAddress((void**)&SU, g_SU);

    cudaFuncSetAttribute(attn_kernel, cudaFuncAttributeMaxDynamicSharedMemorySize,
                         (int)sizeof(AttnSmem));

    qkv_kernel<<<dim3(Cc / 128, Mr / 128, 3), 256>>>(q, Wq, bq, Wk, bk, Wv, bv, Qh, Kh, Vh);
    attn_kernel<<<dim3(Tc / QT, BHc), 256, sizeof(AttnSmem)>>>(Qh, Kh, Vh, Yb, SU);
    sgemm_kernel<<<dim3(Cc / 128, Mr / 128), 256>>>(Yb, Wp, bp, (float*)d_out);
}

// round 13
// speedup vs baseline: 2.7116x; 1.4273x over previous
#include <cuda_runtime.h>

#define Bc 2
#define Tc 2048
#define Cc 512
#define Hc 8
#define HDc 64
#define TOPKc 64
#define BHc (Bc*Hc)
#define Mr (Bc*Tc)

// Scratch (device globals; allocations forbidden)
__device__ float g_Qh[BHc*Tc*HDc];
__device__ float g_Kh[BHc*Tc*HDc];
__device__ float g_Vh[BHc*Tc*HDc];
__device__ float g_Y [Bc*Tc*Cc];
__device__ unsigned g_SU[(size_t)BHc*Tc*Tc];   // scores as ordered uints

// ---------------------------------------------------------------------------
// helpers
// ---------------------------------------------------------------------------
__device__ __forceinline__ unsigned f2u(float f) {
    unsigned b = __float_as_uint(f);
    return b ^ ((unsigned)((int)b >> 31) | 0x80000000u);
}
__device__ __forceinline__ float u2f(unsigned u) {
    unsigned b = (u & 0x80000000u) ? (u ^ 0x80000000u) : ~u;
    return __uint_as_float(b);
}

// ---------------------------------------------------------------------------
// Fused QKV GEMM (round-8 exact, measured 157us): BM=BN=128, BK=8, 256 thr,
// scalar FFMA 8x8 micro, double buffer. z==2 (V): fused per-head row-norm.
// ---------------------------------------------------------------------------
__global__ void __launch_bounds__(256, 2)
qkv_kernel(const float* __restrict__ A,
           const float* __restrict__ Wq, const float* __restrict__ bq,
           const float* __restrict__ Wk, const float* __restrict__ bk,
           const float* __restrict__ Wv, const float* __restrict__ bv,
           float* __restrict__ Qh, float* __restrict__ Kh, float* __restrict__ Vh)
{
    int z = blockIdx.z;
    const float* W    = (z == 0) ? Wq : (z == 1) ? Wk : Wv;
    const float* bias = (z == 0) ? bq : (z == 1) ? bk : bv;
    float* out        = (z == 0) ? Qh : (z == 1) ? Kh : Vh;

    __shared__ float As[2][8][128];
    __shared__ float Bs[2][8][128];

    int tid = threadIdx.x;
    int bm = blockIdx.y * 128;
    int bn = blockIdx.x * 128;
    int ty = tid >> 4;
    int tx = tid & 15;

    int arow = tid >> 1;
    int akq  = (tid & 1) * 4;
    int brow = tid >> 5;
    int bcol = (tid & 31) * 4;

    const float* Ag = A + (size_t)(bm + arow) * Cc + akq;
    const float* Wg = W + (size_t)brow * Cc + bn + bcol;

    float acc[8][8];
    #pragma unroll
    for (int i = 0; i < 8; i++)
        #pragma unroll
        for (int j = 0; j < 8; j++) acc[i][j] = 0.f;

    {
        float4 av = *reinterpret_cast<const float4*>(Ag);
        float4 bv4 = *reinterpret_cast<const float4*>(Wg);
        As[0][akq + 0][arow] = av.x;
        As[0][akq + 1][arow] = av.y;
        As[0][akq + 2][arow] = av.z;
        As[0][akq + 3][arow] = av.w;
        *reinterpret_cast<float4*>(&Bs[0][brow][bcol]) = bv4;
    }
    __syncthreads();

    #pragma unroll 1
    for (int kb = 0; kb < 64; kb++) {
        int cur = kb & 1;
        float4 an, bnv;
        if (kb < 63) {
            an  = *reinterpret_cast<const float4*>(Ag + (kb + 1) * 8);
            bnv = *reinterpret_cast<const float4*>(Wg + (size_t)(kb + 1) * 8 * Cc);
        }
        #pragma unroll
        for (int k = 0; k < 8; k++) {
            float4 a0 = *reinterpret_cast<const float4*>(&As[cur][k][ty * 4]);
            float4 a1 = *reinterpret_cast<const float4*>(&As[cur][k][64 + ty * 4]);
            float4 b0 = *reinterpret_cast<const float4*>(&Bs[cur][k][tx * 4]);
            float4 b1 = *reinterpret_cast<const float4*>(&Bs[cur][k][64 + tx * 4]);
            float a[8] = {a0.x, a0.y, a0.z, a0.w, a1.x, a1.y, a1.z, a1.w};
            float b[8] = {b0.x, b0.y, b0.z, b0.w, b1.x, b1.y, b1.z, b1.w};
            #pragma unroll
            for (int i = 0; i < 8; i++)
                #pragma unroll
                for (int j = 0; j < 8; j++)
                    acc[i][j] += a[i] * b[j];
        }
        if (kb < 63) {
            int nxt = cur ^ 1;
            As[nxt][akq + 0][arow] = an.x;
            As[nxt][akq + 1][arow] = an.y;
            As[nxt][akq + 2][arow] = an.z;
            As[nxt][akq + 3][arow] = an.w;
            *reinterpret_cast<float4*>(&Bs[nxt][brow][bcol]) = bnv;
            __syncthreads();
        }
    }

    float4 bia0 = *reinterpret_cast<const float4*>(bias + bn + tx * 4);
    float4 bia1 = *reinterpret_cast<const float4*>(bias + bn + 64 + tx * 4);
    #pragma unroll
    for (int i = 0; i < 8; i++) {
        int r = (i < 4) ? (ty * 4 + i) : (64 + ty * 4 + (i - 4));
        int mrow = bm + r;
        int b = mrow >> 11;
        int t = mrow & (Tc - 1);
        float4 o0 = make_float4(acc[i][0] + bia0.x, acc[i][1] + bia0.y,
                                acc[i][2] + bia0.z, acc[i][3] + bia0.w);
        float4 o1 = make_float4(acc[i][4] + bia1.x, acc[i][5] + bia1.y,
                                acc[i][6] + bia1.z, acc[i][7] + bia1.w);
        if (z == 2) {
            float ss0 = o0.x*o0.x + o0.y*o0.y + o0.z*o0.z + o0.w*o0.w;
            float ss1 = o1.x*o1.x + o1.y*o1.y + o1.z*o1.z + o1.w*o1.w;
            #pragma unroll
            for (int off = 8; off; off >>= 1) {
                ss0 += __shfl_xor_sync(0xffffffffu, ss0, off);
                ss1 += __shfl_xor_sync(0xffffffffu, ss1, off);
            }
            float sc0 = 1.0f / fmaxf(sqrtf(ss0), 1e-12f);
            float sc1 = 1.0f / fmaxf(sqrtf(ss1), 1e-12f);
            o0.x *= sc0; o0.y *= sc0; o0.z *= sc0; o0.w *= sc0;
            o1.x *= sc1; o1.y *= sc1; o1.z *= sc1; o1.w *= sc1;
        }
        int n0 = bn + tx * 4;       int h0 = n0 >> 6, d0 = n0 & 63;
        int n1 = bn + 64 + tx * 4;  int h1 = n1 >> 6, d1 = n1 & 63;
        *reinterpret_cast<float4*>(out + ((size_t)((b * Hc + h0) * Tc + t) << 6) + d0) = o0;
        *reinterpret_cast<float4*>(out + ((size_t)((b * Hc + h1) * Tc + t) << 6) + d1) = o1;
    }
}

// ---------------------------------------------------------------------------
// Output projection GEMM (row-major out), scalar FFMA (round-8 exact).
// ---------------------------------------------------------------------------
__global__ void __launch_bounds__(256, 2)
sgemm_kernel(const float* __restrict__ A, const float* __restrict__ W,
             const float* __restrict__ bias, float* __restrict__ out)
{
    __shared__ float As[2][8][128];
    __shared__ float Bs[2][8][128];

    int tid = threadIdx.x;
    int bm = blockIdx.y * 128;
    int bn = blockIdx.x * 128;
    int ty = tid >> 4;
    int tx = tid & 15;

    int arow = tid >> 1;
    int akq  = (tid & 1) * 4;
    int brow = tid >> 5;
    int bcol = (tid & 31) * 4;

    const float* Ag = A + (size_t)(bm + arow) * Cc + akq;
    const float* Wg = W + (size_t)brow * Cc + bn + bcol;

    float acc[8][8];
    #pragma unroll
    for (int i = 0; i < 8; i++)
        #pragma unroll
        for (int j = 0; j < 8; j++) acc[i][j] = 0.f;

    {
        float4 av = *reinterpret_cast<const float4*>(Ag);
        float4 bv4 = *reinterpret_cast<const float4*>(Wg);
        As[0][akq + 0][arow] = av.x;
        As[0][akq + 1][arow] = av.y;
        As[0][akq + 2][arow] = av.z;
        As[0][akq + 3][arow] = av.w;
        *reinterpret_cast<float4*>(&Bs[0][brow][bcol]) = bv4;
    }
    __syncthreads();

    #pragma unroll 1
    for (int kb = 0; kb < 64; kb++) {
        int cur = kb & 1;
        float4 an, bnv;
        if (kb < 63) {
            an  = *reinterpret_cast<const float4*>(Ag + (kb + 1) * 8);
            bnv = *reinterpret_cast<const float4*>(Wg + (size_t)(kb + 1) * 8 * Cc);
        }
        #pragma unroll
        for (int k = 0; k < 8; k++) {
            float4 a0 = *reinterpret_cast<const float4*>(&As[cur][k][ty * 4]);
            float4 a1 = *reinterpret_cast<const float4*>(&As[cur][k][64 + ty * 4]);
            float4 b0 = *reinterpret_cast<const float4*>(&Bs[cur][k][tx * 4]);
            float4 b1 = *reinterpret_cast<const float4*>(&Bs[cur][k][64 + tx * 4]);
            float a[8] = {a0.x, a0.y, a0.z, a0.w, a1.x, a1.y, a1.z, a1.w};
            float b[8] = {b0.x, b0.y, b0.z, b0.w, b1.x, b1.y, b1.z, b1.w};
            #pragma unroll
            for (int i = 0; i < 8; i++)
                #pragma unroll
                for (int j = 0; j < 8; j++)
                    acc[i][j] += a[i] * b[j];
        }
        if (kb < 63) {
            int nxt = cur ^ 1;
            As[nxt][akq + 0][arow] = an.x;
            As[nxt][akq + 1][arow] = an.y;
            As[nxt][akq + 2][arow] = an.z;
            As[nxt][akq + 3][arow] = an.w;
            *reinterpret_cast<float4*>(&Bs[nxt][brow][bcol]) = bnv;
            __syncthreads();
        }
    }

    float4 bia0 = *reinterpret_cast<const float4*>(bias + bn + tx * 4);
    float4 bia1 = *reinterpret_cast<const float4*>(bias + bn + 64 + tx * 4);
    #pragma unroll
    for (int i = 0; i < 8; i++) {
        int r = (i < 4) ? (ty * 4 + i) : (64 + ty * 4 + (i - 4));
        int mrow = bm + r;
        float4 o0 = make_float4(acc[i][0] + bia0.x, acc[i][1] + bia0.y,
                                acc[i][2] + bia0.z, acc[i][3] + bia0.w);
        float4 o1 = make_float4(acc[i][4] + bia1.x, acc[i][5] + bia1.y,
                                acc[i][6] + bia1.z, acc[i][7] + bia1.w);
        *reinterpret_cast<float4*>(out + (size_t)mrow * Cc + bn + tx * 4) = o0;
        *reinterpret_cast<float4*>(out + (size_t)mrow * Cc + bn + 64 + tx * 4) = o1;
    }
}

// ---------------------------------------------------------------------------
// Score GEMM: su[q][k] = f2u( (Q[q,:] . K[k,:]) * 0.125 ) for one 128x128
// tile per block. Both operands [128 x 64] row-major; same staging as
// qkv_kernel with 8 d-chunks. Upper-triangle tiles exit immediately.
// Entries k > qi within diagonal tiles are garbage but never read.
// ---------------------------------------------------------------------------
__global__ void __launch_bounds__(256, 2)
score_kernel(const float* __restrict__ Qh, const float* __restrict__ Kh,
             unsigned* __restrict__ gsu)
{
    if (blockIdx.x > blockIdx.y) return;   // fully-masked causal tile
    int bh = blockIdx.z;
    int q0 = blockIdx.y * 128;
    int k0 = blockIdx.x * 128;

    __shared__ float As[2][8][128];
    __shared__ float Bs[2][8][128];

    int tid = threadIdx.x;
    int ty = tid >> 4;
    int tx = tid & 15;

    int arow = tid >> 1;          // 0..127
    int akq  = (tid & 1) * 4;     // 0 or 4

    const float* Ag = Qh + ((size_t)(bh * Tc + q0) + arow) * HDc + akq;
    const float* Bg = Kh + ((size_t)(bh * Tc + k0) + arow) * HDc + akq;

    float acc[8][8];
    #pragma unroll
    for (int i = 0; i < 8; i++)
        #pragma unroll
        for (int j = 0; j < 8; j++) acc[i][j] = 0.f;

    {
        float4 av = *reinterpret_cast<const float4*>(Ag);
        float4 bv = *reinterpret_cast<const float4*>(Bg);
        As[0][akq + 0][arow] = av.x;
        As[0][akq + 1][arow] = av.y;
        As[0][akq + 2][arow] = av.z;
        As[0][akq + 3][arow] = av.w;
        Bs[0][akq + 0][arow] = bv.x;
        Bs[0][akq + 1][arow] = bv.y;
        Bs[0][akq + 2][arow] = bv.z;
        Bs[0][akq + 3][arow] = bv.w;
    }
    __syncthreads();

    #pragma unroll 1
    for (int kb = 0; kb < 8; kb++) {
        int cur = kb & 1;
        float4 an, bn;
        if (kb < 7) {
            an = *reinterpret_cast<const float4*>(Ag + (kb + 1) * 8);
            bn = *reinterpret_cast<const float4*>(Bg + (kb + 1) * 8);
        }
        #pragma unroll
        for (int k = 0; k < 8; k++) {
            float4 a0 = *reinterpret_cast<const float4*>(&As[cur][k][ty * 4]);
            float4 a1 = *reinterpret_cast<const float4*>(&As[cur][k][64 + ty * 4]);
            float4 b0 = *reinterpret_cast<const float4*>(&Bs[cur][k][tx * 4]);
            float4 b1 = *reinterpret_cast<const float4*>(&Bs[cur][k][64 + tx * 4]);
            float a[8] = {a0.x, a0.y, a0.z, a0.w, a1.x, a1.y, a1.z, a1.w};
            float b[8] = {b0.x, b0.y, b0.z, b0.w, b1.x, b1.y, b1.z, b1.w};
            #pragma unroll
            for (int i = 0; i < 8; i++)
                #pragma unroll
                for (int j = 0; j < 8; j++)
                    acc[i][j] += a[i] * b[j];
        }
        if (kb < 7) {
            int nxt = cur ^ 1;
            As[nxt][akq + 0][arow] = an.x;
            As[nxt][akq + 1][arow] = an.y;
            As[nxt][akq + 2][arow] = an.z;
            As[nxt][akq + 3][arow] = an.w;
            Bs[nxt][akq + 0][arow] = bn.x;
            Bs[nxt][akq + 1][arow] = bn.y;
            Bs[nxt][akq + 2][arow] = bn.z;
            Bs[nxt][akq + 3][arow] = bn.w;
            __syncthreads();
        }
    }

    #pragma unroll
    for (int i = 0; i < 8; i++) {
        int r = (i < 4) ? (ty * 4 + i) : (64 + ty * 4 + (i - 4));
        unsigned* dst = gsu + (size_t)(bh * Tc + q0 + r) * Tc + k0;
        uint4 u0, u1;
        u0.x = f2u(acc[i][0] * 0.125f); u0.y = f2u(acc[i][1] * 0.125f);
        u0.z = f2u(acc[i][2] * 0.125f); u0.w = f2u(acc[i][3] * 0.125f);
        u1.x = f2u(acc[i][4] * 0.125f); u1.y = f2u(acc[i][5] * 0.125f);
        u1.z = f2u(acc[i][6] * 0.125f); u1.w = f2u(acc[i][7] * 0.125f);
        *reinterpret_cast<uint4*>(dst + tx * 4)      = u0;
        *reinterpret_cast<uint4*>(dst + 64 + tx * 4) = u1;
    }
}

// ---------------------------------------------------------------------------
// Select kernel: warp <-> query row, fully warp-local (no __syncthreads).
// 32 KB smem -> 6 blocks/SM = 48 warps (3x the fused kernel's occupancy).
// r8-proven logic: 4-pass byte radix (colliding atomics), ballot compaction,
// softmax -> dense probs, sparse PV.
// ---------------------------------------------------------------------------
struct SelSmem {
    int hist[8][256];          // 8 KB
    unsigned short sidx[8][512]; // 8 KB
    float prob[8][512];        // 16 KB
};

__global__ void __launch_bounds__(256, 6)
select_kernel(const unsigned* __restrict__ gsu, const float* __restrict__ V,
              float* __restrict__ Y)
{
    __shared__ SelSmem S;

    int warp = threadIdx.x >> 5;
    int lane = threadIdx.x & 31;

    int bh = blockIdx.y;
    int qi = ((int)gridDim.x - 1 - (int)blockIdx.x) * 8 + warp;  // long rows first
    int n = qi + 1;

    const unsigned* su = gsu + (size_t)(bh * Tc + qi) * Tc;
    const float* Vb = V + (size_t)bh * Tc * HDc;
    int* hist = S.hist[warp];

    // ---- exact rank-64 threshold: 4-pass byte radix
    unsigned thrU = 0u;
    if (n > TOPKc) {
        unsigned pref = 0u; int need = TOPKc;
        #pragma unroll 1
        for (int by = 3; by >= 0; --by) {
            int sh = by * 8;
            #pragma unroll
            for (int b = lane; b < 256; b += 32) hist[b] = 0;
            __syncwarp();
            if (by == 3) {
                for (int k = lane; k < n; k += 32)
                    atomicAdd(&hist[su[k] >> 24], 1);
            } else {
                unsigned hp = pref >> (sh + 8);
                for (int k = lane; k < n; k += 32) {
                    unsigned u = su[k];
                    if ((u >> (sh + 8)) == hp)
                        atomicAdd(&hist[(u >> sh) & 255u], 1);
                }
            }
            __syncwarp();
            int s = 0;
            #pragma unroll
            for (int j = 0; j < 8; j++) s += hist[255 - lane * 8 - j];
            int cum = s;
            #pragma unroll
            for (int off = 1; off < 32; off <<= 1) {
                int v = __shfl_up_sync(0xffffffffu, cum, off);
                if (lane >= off) cum += v;
            }
            unsigned bal = __ballot_sync(0xffffffffu, cum >= need);
            int selL = __ffs(bal) - 1;
            int above = __shfl_sync(0xffffffffu, cum - s, selL);
            int sneed = need - above;
            int res = 0;
            if (lane == selL) {
                int c = 0;
                #pragma unroll 1
                for (int j = 0; j < 8; j++) {
                    int b = 255 - selL * 8 - j;
                    int h = hist[b];
                    if (c + h >= sneed) { res = (b << 16) | (sneed - c); break; }
                    c += h;
                }
            }
            res = __shfl_sync(0xffffffffu, res, selL);
            pref |= (unsigned)(res >> 16) << sh;
            need = res & 0xffff;
        }
        thrU = pref;
    }
    __syncwarp();

    // ---- ballot compaction (ordered) + row max
    unsigned short* sidx = S.sidx[warp];
    int m = 0; unsigned umax = 0u;
    #pragma unroll 1
    for (int k0 = 0; k0 < n; k0 += 32) {
        int k = k0 + lane;
        bool a = k < n;
        unsigned u = a ? su[k] : 0u;
        umax = max(umax, u);
        bool keep = a && (u >= thrU);
        unsigned bal = __ballot_sync(0xffffffffu, keep);
        if (keep) {
            int pos = m + __popc(bal & ((1u << lane) - 1u));
            if (pos < 512) sidx[pos] = (unsigned short)k;
        }
        m += __popc(bal);
    }
    if (m > 512) m = 512;
    #pragma unroll
    for (int off = 16; off; off >>= 1)
        umax = max(umax, __shfl_xor_sync(0xffffffffu, umax, off));

    // ---- softmax over survivors -> dense prob buffer
    float maxf = u2f(umax);
    float lsum = 0.f;
    for (int j = lane; j < m; j += 32) {
        int k = sidx[j];
        float p = __expf(u2f(su[k]) - maxf);
        S.prob[warp][j] = p;
        lsum += p;
    }
    __syncwarp();
    #pragma unroll
    for (int off = 16; off; off >>= 1) lsum += __shfl_xor_sync(0xffffffffu, lsum, off);
    float rinv = 1.0f / lsum;

    // ---- sparse PV
    const float2* V2 = reinterpret_cast<const float2*>(Vb);
    const float* pr = S.prob[warp];
    float2 y = make_float2(0.f, 0.f);
    int j = 0;
    for (; j + 4 <= m; j += 4) {
        int k0 = sidx[j + 0], k1 = sidx[j + 1], k2 = sidx[j + 2], k3 = sidx[j + 3];
        float p0 = pr[j + 0], p1 = pr[j + 1], p2 = pr[j + 2], p3 = pr[j + 3];
        float2 v0 = V2[(size_t)k0 * 32 + lane];
        float2 v1 = V2[(size_t)k1 * 32 + lane];
        float2 v2 = V2[(size_t)k2 * 32 + lane];
        float2 v3 = V2[(size_t)k3 * 32 + lane];
        y.x += p0 * v0.x + p1 * v1.x + p2 * v2.x + p3 * v3.x;
        y.y += p0 * v0.y + p1 * v1.y + p2 * v2.y + p3 * v3.y;
    }
    for (; j < m; j++) {
        int k = sidx[j];
        float p = pr[j];
        float2 v = V2[(size_t)k * 32 + lane];
        y.x += p * v.x; y.y += p * v.y;
    }
    int b = bh >> 3, h = bh & 7;
    *reinterpret_cast<float2*>(Y + (size_t)(b * Tc + qi) * Cc + h * HDc + lane * 2) =
        make_float2(y.x * rinv, y.y * rinv);
}

// ---------------------------------------------------------------------------
extern "C" void kernel_launch(void* const* d_in, const int* in_sizes, int n_in,
                              void* d_out, int out_size)
{
    const float* q  = (const float*)d_in[0];
    const float* Wq = (const float*)d_in[2];
    const float* bq = (const float*)d_in[3];
    const float* Wk = (const float*)d_in[4];
    const float* bk = (const float*)d_in[5];
    const float* Wv = (const float*)d_in[6];
    const float* bv = (const float*)d_in[7];
    const float* Wp = (const float*)d_in[8];
    const float* bp = (const float*)d_in[9];

    float *Qh, *Kh, *Vh, *Yb;
    unsigned* SU;
    cudaGetSymbolAddress((void**)&Qh, g_Qh);
    cudaGetSymbolAddress((void**)&Kh, g_Kh);
    cudaGetSymbolAddress((void**)&Vh, g_Vh);
    cudaGetSymbolAddress((void**)&Yb, g_Y);
    cudaGetSymbolAddress((void**)&SU, g_SU);

    qkv_kernel<<<dim3(Cc / 128, Mr / 128, 3), 256>>>(q, Wq, bq, Wk, bk, Wv, bv, Qh, Kh, Vh);
    score_kernel<<<dim3(Tc / 128, Tc / 128, BHc), 256>>>(Qh, Kh, SU);
    select_kernel<<<dim3(Tc / 8, BHc), 256>>>(SU, Vh, Yb);
    sgemm_kernel<<<dim3(Cc / 128, Mr / 128), 256>>>(Yb, Wp, bp, (float*)d_out);
}